// round 3
// baseline (speedup 1.0000x reference)
#include <cuda_runtime.h>
#include <math.h>

// Problem constants
#define BB   2
#define SS   2048
#define DD   2048
#define NH   16
#define DH   128
#define FFN  5632
#define ROWS (BB*SS)          // 4096
#define E3   (3*NH*DH)        // 6144
#define EPS  1e-5f

// ---------------------------------------------------------------------------
// Scratch (device globals; allocation-free per harness rules)
// ---------------------------------------------------------------------------
__device__ float g_x     [ROWS*DD];                 //  33.5 MB  LN1 out
__device__ float g_qkv   [ROWS*E3];                 // 100.7 MB  qkv (RoPE in place)
__device__ float g_scores[(size_t)BB*NH*SS*SS];     // 536.9 MB  attention scores
__device__ float g_ctx   [ROWS*DD];                 //  33.5 MB  attn context
__device__ float g_h1    [ROWS*DD];                 //  33.5 MB  hidden + attn_out
__device__ float g_x2    [ROWS*DD];                 //  33.5 MB  LN2 out
__device__ float g_ab    [ROWS*2*FFN];              // 184.5 MB  fc_in out
__device__ float g_gate  [ROWS*FFN];                //  92.3 MB  silu(a)*b

// ---------------------------------------------------------------------------
// LayerNorm: one block per row (D = 2048, 256 threads x 8 elements)
// ---------------------------------------------------------------------------
__global__ void ln_kernel(const float* __restrict__ in,
                          const float* __restrict__ gam,
                          const float* __restrict__ bet,
                          float* __restrict__ out)
{
    __shared__ float shs[8], shq[8];
    const int row = blockIdx.x;
    const int tid = threadIdx.x;
    const float* xr = in + (size_t)row * DD;

    float4 v0 = *(const float4*)(xr + tid * 4);
    float4 v1 = *(const float4*)(xr + 1024 + tid * 4);

    float s = v0.x + v0.y + v0.z + v0.w + v1.x + v1.y + v1.z + v1.w;
    float q = v0.x*v0.x + v0.y*v0.y + v0.z*v0.z + v0.w*v0.w
            + v1.x*v1.x + v1.y*v1.y + v1.z*v1.z + v1.w*v1.w;

    #pragma unroll
    for (int o = 16; o; o >>= 1) {
        s += __shfl_down_sync(0xffffffffu, s, o);
        q += __shfl_down_sync(0xffffffffu, q, o);
    }
    const int w = tid >> 5, l = tid & 31;
    if (l == 0) { shs[w] = s; shq[w] = q; }
    __syncthreads();
    if (tid == 0) {
        float ts = 0.f, tq = 0.f;
        #pragma unroll
        for (int i = 0; i < 8; i++) { ts += shs[i]; tq += shq[i]; }
        shs[0] = ts; shq[0] = tq;
    }
    __syncthreads();

    const float mean = shs[0] * (1.0f / DD);
    const float var  = shq[0] * (1.0f / DD) - mean * mean;
    const float inv  = 1.0f / sqrtf(var + EPS);

    float4 g0 = *(const float4*)(gam + tid * 4);
    float4 g1 = *(const float4*)(gam + 1024 + tid * 4);
    float4 b0 = *(const float4*)(bet + tid * 4);
    float4 b1 = *(const float4*)(bet + 1024 + tid * 4);

    float4 o0, o1;
    o0.x = (v0.x - mean) * inv * g0.x + b0.x;
    o0.y = (v0.y - mean) * inv * g0.y + b0.y;
    o0.z = (v0.z - mean) * inv * g0.z + b0.z;
    o0.w = (v0.w - mean) * inv * g0.w + b0.w;
    o1.x = (v1.x - mean) * inv * g1.x + b1.x;
    o1.y = (v1.y - mean) * inv * g1.y + b1.y;
    o1.z = (v1.z - mean) * inv * g1.z + b1.z;
    o1.w = (v1.w - mean) * inv * g1.w + b1.w;

    float* yr = out + (size_t)row * DD;
    *(float4*)(yr + tid * 4)        = o0;
    *(float4*)(yr + 1024 + tid * 4) = o1;
}

// ---------------------------------------------------------------------------
// RoPE (in place on q,k halves of qkv). inv_freq via fp64 exp -> fp32 cast.
// thread handles one (row, head, i<64) rotation pair for q AND k.
// ---------------------------------------------------------------------------
__global__ void rope_kernel(float* __restrict__ qkv, const int* __restrict__ pid)
{
    __shared__ float sinv[64];
    const int tid = threadIdx.x;
    if (tid < 64)
        sinv[tid] = (float)exp(-((double)tid / 64.0) * 9.210340371976184); // ln(1e4)
    __syncthreads();

    const int idx = blockIdx.x * 256 + tid;   // ROWS*NH*64 total, exact multiple
    const int i   = idx & 63;
    const int h   = (idx >> 6) & 15;
    const int row = idx >> 10;

    const float f = (float)pid[row] * sinv[i];
    float sv, cv;
    sincosf(f, &sv, &cv);

    const size_t base = (size_t)row * E3 + (size_t)h * 384;
    float q0 = qkv[base + i],       q1 = qkv[base + 64 + i];
    qkv[base + i]        = q0 * cv - q1 * sv;
    qkv[base + 64 + i]   = q1 * cv + q0 * sv;
    float k0 = qkv[base + 128 + i], k1 = qkv[base + 192 + i];
    qkv[base + 128 + i]  = k0 * cv - k1 * sv;
    qkv[base + 192 + i]  = k1 * cv + k0 * sv;
}

// ---------------------------------------------------------------------------
// Row softmax with mask (mask bytes; nonzero -> -1e4). One block per row.
// ---------------------------------------------------------------------------
__global__ void softmax_kernel(float* __restrict__ sc,
                               const unsigned char* __restrict__ mask)
{
    __shared__ float red[8];
    const long long row = blockIdx.x;                 // (b*NH+h)*SS + q
    float* p = sc + row * (long long)SS;
    const int b  = (int)(row >> 15);                  // / (NH*SS)
    const int qp = (int)(row & (SS - 1));
    const unsigned char* mr = mask + (size_t)b * SS * SS + (size_t)qp * SS;
    const int tid = threadIdx.x;

    float4 a0 = *(const float4*)(p + tid * 4);
    float4 a1 = *(const float4*)(p + 1024 + tid * 4);
    uchar4 m0 = *(const uchar4*)(mr + tid * 4);
    uchar4 m1 = *(const uchar4*)(mr + 1024 + tid * 4);

    float v[8];
    v[0] = m0.x ? -10000.f : a0.x;  v[1] = m0.y ? -10000.f : a0.y;
    v[2] = m0.z ? -10000.f : a0.z;  v[3] = m0.w ? -10000.f : a0.w;
    v[4] = m1.x ? -10000.f : a1.x;  v[5] = m1.y ? -10000.f : a1.y;
    v[6] = m1.z ? -10000.f : a1.z;  v[7] = m1.w ? -10000.f : a1.w;

    float mx = v[0];
    #pragma unroll
    for (int i = 1; i < 8; i++) mx = fmaxf(mx, v[i]);
    #pragma unroll
    for (int o = 16; o; o >>= 1) mx = fmaxf(mx, __shfl_down_sync(0xffffffffu, mx, o));
    const int w = tid >> 5, l = tid & 31;
    if (l == 0) red[w] = mx;
    __syncthreads();
    if (tid == 0) {
        float t = red[0];
        #pragma unroll
        for (int i = 1; i < 8; i++) t = fmaxf(t, red[i]);
        red[0] = t;
    }
    __syncthreads();
    mx = red[0];
    __syncthreads();

    float sum = 0.f;
    #pragma unroll
    for (int i = 0; i < 8; i++) { v[i] = expf(v[i] - mx); sum += v[i]; }
    #pragma unroll
    for (int o = 16; o; o >>= 1) sum += __shfl_down_sync(0xffffffffu, sum, o);
    if (l == 0) red[w] = sum;
    __syncthreads();
    if (tid == 0) {
        float t = 0.f;
        #pragma unroll
        for (int i = 0; i < 8; i++) t += red[i];
        red[0] = t;
    }
    __syncthreads();
    const float r = 1.0f / red[0];

    a0.x = v[0] * r; a0.y = v[1] * r; a0.z = v[2] * r; a0.w = v[3] * r;
    a1.x = v[4] * r; a1.y = v[5] * r; a1.z = v[6] * r; a1.w = v[7] * r;
    *(float4*)(p + tid * 4)        = a0;
    *(float4*)(p + 1024 + tid * 4) = a1;
}

// ---------------------------------------------------------------------------
// SwiGLU: g = silu(a) * b   (a = ab[:, :FFN], b = ab[:, FFN:])
// ---------------------------------------------------------------------------
__global__ void swiglu_kernel(const float* __restrict__ ab, float* __restrict__ g)
{
    const int c = blockIdx.x * 256 + threadIdx.x;   // FFN = 22*256 exact
    const int r = blockIdx.y;
    const size_t base = (size_t)r * (2 * FFN);
    const float a = ab[base + c];
    const float b = ab[base + FFN + c];
    g[(size_t)r * FFN + c] = (a / (1.0f + expf(-a))) * b;
}

// ---------------------------------------------------------------------------
// fp32 SGEMM: C = alpha * A(.)B (+ R),   128x128x16 tiles, double buffered.
// A: [M,K] row-major.  B: [K,N] row-major (TRANSB=false)  or  [N,K] (TRANSB=true).
// Batched via blockIdx.z: z -> (zb = z/nh, zh = z%nh), element-offsets per dim.
// All M,N,K used here are exact multiples of the tile dims (no bounds checks).
// ---------------------------------------------------------------------------
template<bool TRANSB>
__global__ __launch_bounds__(256, 2)
void gemm_kernel(int M, int N, int K,
                 const float* __restrict__ A, int lda, long long sAb, long long sAh,
                 const float* __restrict__ B, int ldb, long long sBb, long long sBh,
                 float*       __restrict__ C, int ldc, long long sCb, long long sCh,
                 const float* __restrict__ R,
                 float alpha, int nh)
{
    __shared__ float As[2][16][132];
    __shared__ float Bs[2][16][132];

    const int z  = blockIdx.z;
    const int zb = z / nh, zh = z % nh;
    A += (size_t)zb * sAb + (size_t)zh * sAh;
    B += (size_t)zb * sBb + (size_t)zh * sBh;
    C += (size_t)zb * sCb + (size_t)zh * sCh;
    if (R) R += (size_t)zb * sCb + (size_t)zh * sCh;

    const int m0  = blockIdx.y * 128;
    const int n0  = blockIdx.x * 128;
    const int tid = threadIdx.x;
    const int tx  = tid & 15;
    const int ty  = tid >> 4;

    const int ar = tid >> 2;          // 0..63
    const int ac = (tid & 3) << 2;    // 0,4,8,12
    const int br = tid >> 5;          // 0..7
    const int bc = (tid & 31) << 2;   // 0..124

    const float* Ag0 = A + (size_t)(m0 + ar) * lda + ac;
    const float* Ag1 = A + (size_t)(m0 + ar + 64) * lda + ac;
    const float* Bg0;
    const float* Bg1;
    if (TRANSB) {
        Bg0 = B + (size_t)(n0 + ar) * ldb + ac;
        Bg1 = B + (size_t)(n0 + ar + 64) * ldb + ac;
    } else {
        Bg0 = B + (size_t)br * ldb + n0 + bc;
        Bg1 = B + (size_t)(br + 8) * ldb + n0 + bc;
    }

    float acc[8][8];
    #pragma unroll
    for (int i = 0; i < 8; i++)
        #pragma unroll
        for (int j = 0; j < 8; j++) acc[i][j] = 0.f;

    float4 ra0, ra1, rb0, rb1;

#define LOAD_TILE(kt) do {                                                          \
        ra0 = *(const float4*)(Ag0 + (size_t)(kt) * 16);                            \
        ra1 = *(const float4*)(Ag1 + (size_t)(kt) * 16);                            \
        if (TRANSB) {                                                               \
            rb0 = *(const float4*)(Bg0 + (size_t)(kt) * 16);                        \
            rb1 = *(const float4*)(Bg1 + (size_t)(kt) * 16);                        \
        } else {                                                                    \
            rb0 = *(const float4*)(Bg0 + (size_t)(kt) * 16 * ldb);                  \
            rb1 = *(const float4*)(Bg1 + (size_t)(kt) * 16 * ldb);                  \
        }                                                                           \
    } while (0)

#define STORE_TILE(buf) do {                                                        \
        As[buf][ac+0][ar]    = ra0.x; As[buf][ac+1][ar]    = ra0.y;                 \
        As[buf][ac+2][ar]    = ra0.z; As[buf][ac+3][ar]    = ra0.w;                 \
        As[buf][ac+0][ar+64] = ra1.x; As[buf][ac+1][ar+64] = ra1.y;                 \
        As[buf][ac+2][ar+64] = ra1.z; As[buf][ac+3][ar+64] = ra1.w;                 \
        if (TRANSB) {                                                               \
            Bs[buf][ac+0][ar]    = rb0.x; Bs[buf][ac+1][ar]    = rb0.y;             \
            Bs[buf][ac+2][ar]    = rb0.z; Bs[buf][ac+3][ar]    = rb0.w;             \
            Bs[buf][ac+0][ar+64] = rb1.x; Bs[buf][ac+1][ar+64] = rb1.y;             \
            Bs[buf][ac+2][ar+64] = rb1.z; Bs[buf][ac+3][ar+64] = rb1.w;             \
        } else {                                                                    \
            *(float4*)&Bs[buf][br][bc]     = rb0;                                   \
            *(float4*)&Bs[buf][br + 8][bc] = rb1;                                   \
        }                                                                           \
    } while (0)

    const int T = K >> 4;
    LOAD_TILE(0);
    STORE_TILE(0);
    __syncthreads();

    for (int t = 0; t < T; ++t) {
        const int cur = t & 1;
        if (t + 1 < T) LOAD_TILE(t + 1);

        #pragma unroll
        for (int kk = 0; kk < 16; ++kk) {
            float4 a0 = *(const float4*)&As[cur][kk][ty * 4];
            float4 a1 = *(const float4*)&As[cur][kk][64 + ty * 4];
            float4 b0 = *(const float4*)&Bs[cur][kk][tx * 4];
            float4 b1 = *(const float4*)&Bs[cur][kk][64 + tx * 4];
            float av[8] = {a0.x, a0.y, a0.z, a0.w, a1.x, a1.y, a1.z, a1.w};
            float bv[8] = {b0.x, b0.y, b0.z, b0.w, b1.x, b1.y, b1.z, b1.w};
            #pragma unroll
            for (int i = 0; i < 8; i++)
                #pragma unroll
                for (int j = 0; j < 8; j++)
                    acc[i][j] = fmaf(av[i], bv[j], acc[i][j]);
        }

        if (t + 1 < T) {
            STORE_TILE(cur ^ 1);
            __syncthreads();
        }
    }

#undef LOAD_TILE
#undef STORE_TILE

    #pragma unroll
    for (int gi = 0; gi < 2; ++gi)
        #pragma unroll
        for (int i = 0; i < 4; ++i) {
            const int m = m0 + gi * 64 + ty * 4 + i;
            #pragma unroll
            for (int gj = 0; gj < 2; ++gj) {
                const int n = n0 + gj * 64 + tx * 4;
                float4 o;
                o.x = alpha * acc[gi * 4 + i][gj * 4 + 0];
                o.y = alpha * acc[gi * 4 + i][gj * 4 + 1];
                o.z = alpha * acc[gi * 4 + i][gj * 4 + 2];
                o.w = alpha * acc[gi * 4 + i][gj * 4 + 3];
                if (R) {
                    float4 rv = *(const float4*)(R + (size_t)m * ldc + n);
                    o.x += rv.x; o.y += rv.y; o.z += rv.z; o.w += rv.w;
                }
                *(float4*)(C + (size_t)m * ldc + n) = o;
            }
        }
}

// ---------------------------------------------------------------------------
// Launch
// ---------------------------------------------------------------------------
extern "C" void kernel_launch(void* const* d_in, const int* in_sizes, int n_in,
                              void* d_out, int out_size)
{
    const float*         hidden = (const float*)d_in[0];
    const unsigned char* mask   = (const unsigned char*)d_in[1];
    const int*           pos    = (const int*)d_in[2];
    const float*         ln1g   = (const float*)d_in[3];
    const float*         ln1b   = (const float*)d_in[4];
    const float*         Wqkv   = (const float*)d_in[5];
    const float*         Wo     = (const float*)d_in[6];
    const float*         ln2g   = (const float*)d_in[7];
    const float*         ln2b   = (const float*)d_in[8];
    const float*         Wfi    = (const float*)d_in[9];
    const float*         Wfo    = (const float*)d_in[10];
    float*               out    = (float*)d_out;

    float *x, *qkv, *sc, *ctx, *h1, *x2, *ab, *gt;
    cudaGetSymbolAddress((void**)&x,   g_x);
    cudaGetSymbolAddress((void**)&qkv, g_qkv);
    cudaGetSymbolAddress((void**)&sc,  g_scores);
    cudaGetSymbolAddress((void**)&ctx, g_ctx);
    cudaGetSymbolAddress((void**)&h1,  g_h1);
    cudaGetSymbolAddress((void**)&x2,  g_x2);
    cudaGetSymbolAddress((void**)&ab,  g_ab);
    cudaGetSymbolAddress((void**)&gt,  g_gate);

    const long long sQKVb = (long long)SS * E3;      // batch stride inside qkv
    const long long sSCb  = (long long)NH * SS * SS; // batch stride inside scores
    const long long sSCh  = (long long)SS * SS;

    // 1) LN1
    ln_kernel<<<ROWS, 256>>>(hidden, ln1g, ln1b, x);

    // 2) qkv = x @ Wqkv   [4096,6144]
    gemm_kernel<false><<<dim3(E3 / 128, ROWS / 128, 1), 256>>>(
        ROWS, E3, DD, x, DD, 0, 0, Wqkv, E3, 0, 0, qkv, E3, 0, 0,
        nullptr, 1.0f, 1);

    // 3) RoPE on q,k (in place)
    rope_kernel<<<(ROWS * NH * 64) / 256, 256>>>(qkv, pos);

    // 4) scores = (Q @ K^T) / sqrt(DH)   per (b,h): [2048,2048]
    gemm_kernel<true><<<dim3(SS / 128, SS / 128, BB * NH), 256>>>(
        SS, SS, DH,
        qkv,       E3, sQKVb, 384,
        qkv + 128, E3, sQKVb, 384,
        sc,        SS, sSCb,  sSCh,
        nullptr, 0.08838834764831845f, NH);

    // 5) masked softmax over rows
    softmax_kernel<<<BB * NH * SS, 256>>>(sc, mask);

    // 6) ctx = P @ V   per (b,h): [2048,128] -> [B,S,H*DH]
    gemm_kernel<false><<<dim3(1, SS / 128, BB * NH), 256>>>(
        SS, DH, SS,
        sc,        SS, sSCb, sSCh,
        qkv + 256, E3, sQKVb, 384,
        ctx,       DD, (long long)SS * DD, DH,
        nullptr, 1.0f, NH);

    // 7) h1 = hidden + ctx @ Wo
    gemm_kernel<false><<<dim3(DD / 128, ROWS / 128, 1), 256>>>(
        ROWS, DD, DD, ctx, DD, 0, 0, Wo, DD, 0, 0, h1, DD, 0, 0,
        hidden, 1.0f, 1);

    // 8) LN2
    ln_kernel<<<ROWS, 256>>>(h1, ln2g, ln2b, x2);

    // 9) ab = x2 @ Wfc_in   [4096,11264]
    gemm_kernel<false><<<dim3((2 * FFN) / 128, ROWS / 128, 1), 256>>>(
        ROWS, 2 * FFN, DD, x2, DD, 0, 0, Wfi, 2 * FFN, 0, 0, ab, 2 * FFN, 0, 0,
        nullptr, 1.0f, 1);

    // 10) gate = silu(a) * b
    swiglu_kernel<<<dim3(FFN / 256, ROWS), 256>>>(ab, gt);

    // 11) out = h1 + gate @ Wfc_out
    gemm_kernel<false><<<dim3(DD / 128, ROWS / 128, 1), 256>>>(
        ROWS, DD, FFN, gt, FFN, 0, 0, Wfo, DD, 0, 0, out, DD, 0, 0,
        h1, 1.0f, 1);

    (void)in_sizes; (void)n_in; (void)out_size;
}

// round 9
// speedup vs baseline: 2.3066x; 2.3066x over previous
#include <cuda_runtime.h>
#include <math.h>
#include <stdint.h>

// Problem constants
#define BB   2
#define SS   2048
#define DD   2048
#define NH   16
#define DH   128
#define FFN  5632
#define ROWS (BB*SS)          // 4096
#define E3   (3*NH*DH)        // 6144
#define EPS  1e-5f

// ---------------------------------------------------------------------------
// Scratch (device globals; allocation-free per harness rules)
// ---------------------------------------------------------------------------
__device__ float g_x     [ROWS*DD];                 //  33.5 MB  LN1 out
__device__ float g_qkv   [ROWS*E3];                 // 100.7 MB  qkv (RoPE in place)
__device__ float g_scores[(size_t)BB*NH*SS*SS];     // 536.9 MB  attention scores
__device__ float g_ctx   [ROWS*DD];                 //  33.5 MB  attn context
__device__ float g_h1    [ROWS*DD];                 //  33.5 MB  hidden + attn_out
__device__ float g_x2    [ROWS*DD];                 //  33.5 MB  LN2 out
__device__ float g_ab    [ROWS*2*FFN];              // 184.5 MB  fc_in out
__device__ float g_gate  [ROWS*FFN];                //  92.3 MB  silu(a)*b

// ---------------------------------------------------------------------------
// tf32 helpers
// ---------------------------------------------------------------------------
__device__ __forceinline__ float to_tf32(float x) {
    uint32_t u;
    asm("cvt.rna.tf32.f32 %0, %1;" : "=r"(u) : "f"(x));
    return __uint_as_float(u);
}

#define MMA_TF32(c0,c1,c2,c3, a0,a1,a2,a3, b0,b1)                               \
    asm volatile("mma.sync.aligned.m16n8k8.row.col.f32.tf32.tf32.f32 "          \
                 "{%0,%1,%2,%3}, {%4,%5,%6,%7}, {%8,%9}, {%0,%1,%2,%3};"        \
                 : "+f"(c0), "+f"(c1), "+f"(c2), "+f"(c3)                       \
                 : "r"(a0), "r"(a1), "r"(a2), "r"(a3), "r"(b0), "r"(b1))

// ---------------------------------------------------------------------------
// LayerNorm: one block per row (D = 2048, 256 threads x 8 elements)
// ---------------------------------------------------------------------------
__global__ void ln_kernel(const float* __restrict__ in,
                          const float* __restrict__ gam,
                          const float* __restrict__ bet,
                          float* __restrict__ out)
{
    __shared__ float shs[8], shq[8];
    const int row = blockIdx.x;
    const int tid = threadIdx.x;
    const float* xr = in + (size_t)row * DD;

    float4 v0 = *(const float4*)(xr + tid * 4);
    float4 v1 = *(const float4*)(xr + 1024 + tid * 4);

    float s = v0.x + v0.y + v0.z + v0.w + v1.x + v1.y + v1.z + v1.w;
    float q = v0.x*v0.x + v0.y*v0.y + v0.z*v0.z + v0.w*v0.w
            + v1.x*v1.x + v1.y*v1.y + v1.z*v1.z + v1.w*v1.w;

    #pragma unroll
    for (int o = 16; o; o >>= 1) {
        s += __shfl_down_sync(0xffffffffu, s, o);
        q += __shfl_down_sync(0xffffffffu, q, o);
    }
    const int w = tid >> 5, l = tid & 31;
    if (l == 0) { shs[w] = s; shq[w] = q; }
    __syncthreads();
    if (tid == 0) {
        float ts = 0.f, tq = 0.f;
        #pragma unroll
        for (int i = 0; i < 8; i++) { ts += shs[i]; tq += shq[i]; }
        shs[0] = ts; shq[0] = tq;
    }
    __syncthreads();

    const float mean = shs[0] * (1.0f / DD);
    const float var  = shq[0] * (1.0f / DD) - mean * mean;
    const float inv  = 1.0f / sqrtf(var + EPS);

    float4 g0 = *(const float4*)(gam + tid * 4);
    float4 g1 = *(const float4*)(gam + 1024 + tid * 4);
    float4 b0 = *(const float4*)(bet + tid * 4);
    float4 b1 = *(const float4*)(bet + 1024 + tid * 4);

    float4 o0, o1;
    o0.x = (v0.x - mean) * inv * g0.x + b0.x;
    o0.y = (v0.y - mean) * inv * g0.y + b0.y;
    o0.z = (v0.z - mean) * inv * g0.z + b0.z;
    o0.w = (v0.w - mean) * inv * g0.w + b0.w;
    o1.x = (v1.x - mean) * inv * g1.x + b1.x;
    o1.y = (v1.y - mean) * inv * g1.y + b1.y;
    o1.z = (v1.z - mean) * inv * g1.z + b1.z;
    o1.w = (v1.w - mean) * inv * g1.w + b1.w;

    float* yr = out + (size_t)row * DD;
    *(float4*)(yr + tid * 4)        = o0;
    *(float4*)(yr + 1024 + tid * 4) = o1;
}

// ---------------------------------------------------------------------------
// RoPE (in place on q,k halves of qkv).
// ---------------------------------------------------------------------------
__global__ void rope_kernel(float* __restrict__ qkv, const int* __restrict__ pid)
{
    __shared__ float sinv[64];
    const int tid = threadIdx.x;
    if (tid < 64)
        sinv[tid] = (float)exp(-((double)tid / 64.0) * 9.210340371976184); // ln(1e4)
    __syncthreads();

    const int idx = blockIdx.x * 256 + tid;   // ROWS*NH*64 total, exact multiple
    const int i   = idx & 63;
    const int h   = (idx >> 6) & 15;
    const int row = idx >> 10;

    const float f = (float)pid[row] * sinv[i];
    float sv, cv;
    sincosf(f, &sv, &cv);

    const size_t base = (size_t)row * E3 + (size_t)h * 384;
    float q0 = qkv[base + i],       q1 = qkv[base + 64 + i];
    qkv[base + i]        = q0 * cv - q1 * sv;
    qkv[base + 64 + i]   = q1 * cv + q0 * sv;
    float k0 = qkv[base + 128 + i], k1 = qkv[base + 192 + i];
    qkv[base + 128 + i]  = k0 * cv - k1 * sv;
    qkv[base + 192 + i]  = k1 * cv + k0 * sv;
}

// ---------------------------------------------------------------------------
// Row softmax with mask (mask bytes; nonzero -> -1e4). One block per row.
// ---------------------------------------------------------------------------
__global__ void softmax_kernel(float* __restrict__ sc,
                               const unsigned char* __restrict__ mask)
{
    __shared__ float red[8];
    const long long row = blockIdx.x;                 // (b*NH+h)*SS + q
    float* p = sc + row * (long long)SS;
    const int b  = (int)(row >> 15);                  // / (NH*SS)
    const int qp = (int)(row & (SS - 1));
    const unsigned char* mr = mask + (size_t)b * SS * SS + (size_t)qp * SS;
    const int tid = threadIdx.x;

    float4 a0 = *(const float4*)(p + tid * 4);
    float4 a1 = *(const float4*)(p + 1024 + tid * 4);
    uchar4 m0 = *(const uchar4*)(mr + tid * 4);
    uchar4 m1 = *(const uchar4*)(mr + 1024 + tid * 4);

    float v[8];
    v[0] = m0.x ? -10000.f : a0.x;  v[1] = m0.y ? -10000.f : a0.y;
    v[2] = m0.z ? -10000.f : a0.z;  v[3] = m0.w ? -10000.f : a0.w;
    v[4] = m1.x ? -10000.f : a1.x;  v[5] = m1.y ? -10000.f : a1.y;
    v[6] = m1.z ? -10000.f : a1.z;  v[7] = m1.w ? -10000.f : a1.w;

    float mx = v[0];
    #pragma unroll
    for (int i = 1; i < 8; i++) mx = fmaxf(mx, v[i]);
    #pragma unroll
    for (int o = 16; o; o >>= 1) mx = fmaxf(mx, __shfl_down_sync(0xffffffffu, mx, o));
    const int w = tid >> 5, l = tid & 31;
    if (l == 0) red[w] = mx;
    __syncthreads();
    if (tid == 0) {
        float t = red[0];
        #pragma unroll
        for (int i = 1; i < 8; i++) t = fmaxf(t, red[i]);
        red[0] = t;
    }
    __syncthreads();
    mx = red[0];
    __syncthreads();

    float sum = 0.f;
    #pragma unroll
    for (int i = 0; i < 8; i++) { v[i] = expf(v[i] - mx); sum += v[i]; }
    #pragma unroll
    for (int o = 16; o; o >>= 1) sum += __shfl_down_sync(0xffffffffu, sum, o);
    if (l == 0) red[w] = sum;
    __syncthreads();
    if (tid == 0) {
        float t = 0.f;
        #pragma unroll
        for (int i = 0; i < 8; i++) t += red[i];
        red[0] = t;
    }
    __syncthreads();
    const float r = 1.0f / red[0];

    a0.x = v[0] * r; a0.y = v[1] * r; a0.z = v[2] * r; a0.w = v[3] * r;
    a1.x = v[4] * r; a1.y = v[5] * r; a1.z = v[6] * r; a1.w = v[7] * r;
    *(float4*)(p + tid * 4)        = a0;
    *(float4*)(p + 1024 + tid * 4) = a1;
}

// ---------------------------------------------------------------------------
// SwiGLU: g = silu(a) * b
// ---------------------------------------------------------------------------
__global__ void swiglu_kernel(const float* __restrict__ ab, float* __restrict__ g)
{
    const int c = blockIdx.x * 256 + threadIdx.x;   // FFN = 22*256 exact
    const int r = blockIdx.y;
    const size_t base = (size_t)r * (2 * FFN);
    const float a = ab[base + c];
    const float b = ab[base + FFN + c];
    g[(size_t)r * FFN + c] = (a / (1.0f + expf(-a))) * b;
}

// ---------------------------------------------------------------------------
// TF32 tensor-core GEMM: C = alpha * A(.)B (+ R)
// 128x128x16 CTA tile, 256 threads = 8 warps, each warp 64x32 via m16n8k8.
// A: [M,K] row-major.  B: [K,N] (TRANSB=false) or [N,K] (TRANSB=true).
// Batched via blockIdx.z. All dims exact multiples (no bounds checks).
// smem k-major with stride 136 (conflict-free fragment LDS).
// ---------------------------------------------------------------------------
#define SPAD 136

template<bool TRANSB>
__global__ __launch_bounds__(256, 2)
void gemm_tc(int M, int N, int K,
             const float* __restrict__ A, int lda, long long sAb, long long sAh,
             const float* __restrict__ B, int ldb, long long sBb, long long sBh,
             float*       __restrict__ C, int ldc, long long sCb, long long sCh,
             const float* __restrict__ R,
             float alpha, int nh)
{
    __shared__ float As[2][16][SPAD];
    __shared__ float Bs[2][16][SPAD];

    const int z  = blockIdx.z;
    const int zb = z / nh, zh = z % nh;
    A += (size_t)zb * sAb + (size_t)zh * sAh;
    B += (size_t)zb * sBb + (size_t)zh * sBh;
    C += (size_t)zb * sCb + (size_t)zh * sCh;
    if (R) R += (size_t)zb * sCb + (size_t)zh * sCh;

    const int m0  = blockIdx.y * 128;
    const int n0  = blockIdx.x * 128;
    const int tid = threadIdx.x;
    const int lane = tid & 31;
    const int wid  = tid >> 5;
    const int wm = (wid >> 2) * 64;   // 0 / 64
    const int wn = (wid & 3) * 32;    // 0,32,64,96

    // global-load assignments
    const int ar = tid >> 2;          // 0..63
    const int ac = (tid & 3) << 2;    // 0,4,8,12
    const int br = tid >> 5;          // 0..7
    const int bc = (tid & 31) << 2;   // 0..124

    const float* Ag0 = A + (size_t)(m0 + ar) * lda + ac;
    const float* Ag1 = A + (size_t)(m0 + ar + 64) * lda + ac;
    const float* Bg0;
    const float* Bg1;
    if (TRANSB) {
        Bg0 = B + (size_t)(n0 + ar) * ldb + ac;
        Bg1 = B + (size_t)(n0 + ar + 64) * ldb + ac;
    } else {
        Bg0 = B + (size_t)br * ldb + n0 + bc;
        Bg1 = B + (size_t)(br + 8) * ldb + n0 + bc;
    }

    float acc[4][4][4];
    #pragma unroll
    for (int i = 0; i < 4; i++)
        #pragma unroll
        for (int j = 0; j < 4; j++)
            #pragma unroll
            for (int c = 0; c < 4; c++) acc[i][j][c] = 0.f;

    float4 ra0, ra1, rb0, rb1;

#define LOAD_TILE(kt) do {                                                          \
        ra0 = *(const float4*)(Ag0 + (size_t)(kt) * 16);                            \
        ra1 = *(const float4*)(Ag1 + (size_t)(kt) * 16);                            \
        if (TRANSB) {                                                               \
            rb0 = *(const float4*)(Bg0 + (size_t)(kt) * 16);                        \
            rb1 = *(const float4*)(Bg1 + (size_t)(kt) * 16);                        \
        } else {                                                                    \
            rb0 = *(const float4*)(Bg0 + (size_t)(kt) * 16 * ldb);                  \
            rb1 = *(const float4*)(Bg1 + (size_t)(kt) * 16 * ldb);                  \
        }                                                                           \
    } while (0)

#define STORE_TILE(buf) do {                                                        \
        As[buf][ac+0][ar]    = to_tf32(ra0.x); As[buf][ac+1][ar]    = to_tf32(ra0.y);\
        As[buf][ac+2][ar]    = to_tf32(ra0.z); As[buf][ac+3][ar]    = to_tf32(ra0.w);\
        As[buf][ac+0][ar+64] = to_tf32(ra1.x); As[buf][ac+1][ar+64] = to_tf32(ra1.y);\
        As[buf][ac+2][ar+64] = to_tf32(ra1.z); As[buf][ac+3][ar+64] = to_tf32(ra1.w);\
        if (TRANSB) {                                                               \
            Bs[buf][ac+0][ar]    = to_tf32(rb0.x); Bs[buf][ac+1][ar]    = to_tf32(rb0.y);\
            Bs[buf][ac+2][ar]    = to_tf32(rb0.z); Bs[buf][ac+3][ar]    = to_tf32(rb0.w);\
            Bs[buf][ac+0][ar+64] = to_tf32(rb1.x); Bs[buf][ac+1][ar+64] = to_tf32(rb1.y);\
            Bs[buf][ac+2][ar+64] = to_tf32(rb1.z); Bs[buf][ac+3][ar+64] = to_tf32(rb1.w);\
        } else {                                                                    \
            float4 t0, t1;                                                          \
            t0.x = to_tf32(rb0.x); t0.y = to_tf32(rb0.y);                           \
            t0.z = to_tf32(rb0.z); t0.w = to_tf32(rb0.w);                           \
            t1.x = to_tf32(rb1.x); t1.y = to_tf32(rb1.y);                           \
            t1.z = to_tf32(rb1.z); t1.w = to_tf32(rb1.w);                           \
            *(float4*)&Bs[buf][br][bc]     = t0;                                    \
            *(float4*)&Bs[buf][br + 8][bc] = t1;                                    \
        }                                                                           \
    } while (0)

    const int T = K >> 4;
    LOAD_TILE(0);
    STORE_TILE(0);
    __syncthreads();

    const int kq = lane & 3;        // k within 4
    const int mq = lane >> 2;       // 0..7

    for (int t = 0; t < T; ++t) {
        const int cur = t & 1;
        if (t + 1 < T) LOAD_TILE(t + 1);

        #pragma unroll
        for (int k8 = 0; k8 < 16; k8 += 8) {
            const int kr = k8 + kq;
            uint32_t af[4][4], bf[4][2];
            #pragma unroll
            for (int mi = 0; mi < 4; mi++) {
                const int mb = wm + mi * 16 + mq;
                af[mi][0] = __float_as_uint(As[cur][kr][mb]);
                af[mi][1] = __float_as_uint(As[cur][kr][mb + 8]);
                af[mi][2] = __float_as_uint(As[cur][kr + 4][mb]);
                af[mi][3] = __float_as_uint(As[cur][kr + 4][mb + 8]);
            }
            #pragma unroll
            for (int nj = 0; nj < 4; nj++) {
                const int nb = wn + nj * 8 + mq;
                bf[nj][0] = __float_as_uint(Bs[cur][kr][nb]);
                bf[nj][1] = __float_as_uint(Bs[cur][kr + 4][nb]);
            }
            #pragma unroll
            for (int mi = 0; mi < 4; mi++)
                #pragma unroll
                for (int nj = 0; nj < 4; nj++)
                    MMA_TF32(acc[mi][nj][0], acc[mi][nj][1],
                             acc[mi][nj][2], acc[mi][nj][3],
                             af[mi][0], af[mi][1], af[mi][2], af[mi][3],
                             bf[nj][0], bf[nj][1]);
        }

        if (t + 1 < T) {
            STORE_TILE(cur ^ 1);
            __syncthreads();
        }
    }

#undef LOAD_TILE
#undef STORE_TILE

    // Epilogue: c0,c1 at (row=mq, col=2*kq, +1); c2,c3 at row=mq+8.
    #pragma unroll
    for (int mi = 0; mi < 4; mi++) {
        #pragma unroll
        for (int half = 0; half < 2; half++) {
            const int m = m0 + wm + mi * 16 + mq + half * 8;
            float* crow = C + (size_t)m * ldc;
            const float* rrow = R ? R + (size_t)m * ldc : nullptr;
            #pragma unroll
            for (int nj = 0; nj < 4; nj++) {
                const int n = n0 + wn + nj * 8 + 2 * kq;
                float2 o;
                o.x = alpha * acc[mi][nj][half * 2 + 0];
                o.y = alpha * acc[mi][nj][half * 2 + 1];
                if (R) {
                    float2 rv = *(const float2*)(rrow + n);
                    o.x += rv.x; o.y += rv.y;
                }
                *(float2*)(crow + n) = o;
            }
        }
    }
}

// ---------------------------------------------------------------------------
// Launch
// ---------------------------------------------------------------------------
extern "C" void kernel_launch(void* const* d_in, const int* in_sizes, int n_in,
                              void* d_out, int out_size)
{
    const float*         hidden = (const float*)d_in[0];
    const unsigned char* mask   = (const unsigned char*)d_in[1];
    const int*           pos    = (const int*)d_in[2];
    const float*         ln1g   = (const float*)d_in[3];
    const float*         ln1b   = (const float*)d_in[4];
    const float*         Wqkv   = (const float*)d_in[5];
    const float*         Wo     = (const float*)d_in[6];
    const float*         ln2g   = (const float*)d_in[7];
    const float*         ln2b   = (const float*)d_in[8];
    const float*         Wfi    = (const float*)d_in[9];
    const float*         Wfo    = (const float*)d_in[10];
    float*               out    = (float*)d_out;

    float *x, *qkv, *sc, *ctx, *h1, *x2, *ab, *gt;
    cudaGetSymbolAddress((void**)&x,   g_x);
    cudaGetSymbolAddress((void**)&qkv, g_qkv);
    cudaGetSymbolAddress((void**)&sc,  g_scores);
    cudaGetSymbolAddress((void**)&ctx, g_ctx);
    cudaGetSymbolAddress((void**)&h1,  g_h1);
    cudaGetSymbolAddress((void**)&x2,  g_x2);
    cudaGetSymbolAddress((void**)&ab,  g_ab);
    cudaGetSymbolAddress((void**)&gt,  g_gate);

    const long long sQKVb = (long long)SS * E3;      // batch stride inside qkv
    const long long sSCb  = (long long)NH * SS * SS; // batch stride inside scores
    const long long sSCh  = (long long)SS * SS;

    // 1) LN1
    ln_kernel<<<ROWS, 256>>>(hidden, ln1g, ln1b, x);

    // 2) qkv = x @ Wqkv   [4096,6144]
    gemm_tc<false><<<dim3(E3 / 128, ROWS / 128, 1), 256>>>(
        ROWS, E3, DD, x, DD, 0, 0, Wqkv, E3, 0, 0, qkv, E3, 0, 0,
        nullptr, 1.0f, 1);

    // 3) RoPE on q,k (in place)
    rope_kernel<<<(ROWS * NH * 64) / 256, 256>>>(qkv, pos);

    // 4) scores = (Q @ K^T) / sqrt(DH)   per (b,h): [2048,2048]
    gemm_tc<true><<<dim3(SS / 128, SS / 128, BB * NH), 256>>>(
        SS, SS, DH,
        qkv,       E3, sQKVb, 384,
        qkv + 128, E3, sQKVb, 384,
        sc,        SS, sSCb,  sSCh,
        nullptr, 0.08838834764831845f, NH);

    // 5) masked softmax over rows
    softmax_kernel<<<BB * NH * SS, 256>>>(sc, mask);

    // 6) ctx = P @ V   per (b,h): [2048,128] -> [B,S,H*DH]
    gemm_tc<false><<<dim3(1, SS / 128, BB * NH), 256>>>(
        SS, DH, SS,
        sc,        SS, sSCb, sSCh,
        qkv + 256, E3, sQKVb, 384,
        ctx,       DD, (long long)SS * DD, DH,
        nullptr, 1.0f, NH);

    // 7) h1 = hidden + ctx @ Wo
    gemm_tc<false><<<dim3(DD / 128, ROWS / 128, 1), 256>>>(
        ROWS, DD, DD, ctx, DD, 0, 0, Wo, DD, 0, 0, h1, DD, 0, 0,
        hidden, 1.0f, 1);

    // 8) LN2
    ln_kernel<<<ROWS, 256>>>(h1, ln2g, ln2b, x2);

    // 9) ab = x2 @ Wfc_in   [4096,11264]
    gemm_tc<false><<<dim3((2 * FFN) / 128, ROWS / 128, 1), 256>>>(
        ROWS, 2 * FFN, DD, x2, DD, 0, 0, Wfi, 2 * FFN, 0, 0, ab, 2 * FFN, 0, 0,
        nullptr, 1.0f, 1);

    // 10) gate = silu(a) * b
    swiglu_kernel<<<dim3(FFN / 256, ROWS), 256>>>(ab, gt);

    // 11) out = h1 + gate @ Wfc_out
    gemm_tc<false><<<dim3(DD / 128, ROWS / 128, 1), 256>>>(
        ROWS, DD, FFN, gt, FFN, 0, 0, Wfo, DD, 0, 0, out, DD, 0, 0,
        h1, 1.0f, 1);

    (void)in_sizes; (void)n_in; (void)out_size;
}